// round 10
// baseline (speedup 1.0000x reference)
#include <cuda_runtime.h>
#include <math.h>
#include <limits.h>

// L2loss over bucketized histograms — analytic segment version (R10).
// Sum_p (h1-h2)^2 = sum over segments [x, next(x)) of len*d^2, candidates =
// the 6*256 cum values, deduped at first occurrence. 8 blocks x 192 threads
// = 1536 = one candidate per thread, as ONE CLUSTER.
// R10: cross-block reduce = red.relaxed.cluster into block 0's smem, then a
// remote mbarrier arrive (release). Block 0 try_waits the mbarrier (acquire)
// instead of a second ~490cy cluster barrier round. No global state at all.

namespace {
constexpr int KBINS = 256;
constexpr int NPIX  = 224 * 224;     // 50176
constexpr int TPB   = 192;           // 6 warps (one per scanned array)
constexpr int NENT  = 6 * KBINS;     // 1536 candidate breakpoints
constexpr int NBLK  = NENT / TPB;    // 8 = cluster size
constexpr int NWARP = TPB / 32;      // 6
}

__device__ __forceinline__ unsigned int smem_u32(const void* p) {
    unsigned int a;
    asm("{ .reg .u64 t; cvta.to.shared.u64 t, %1; cvt.u32.u64 %0, t; }"
        : "=r"(a) : "l"(p));
    return a;
}

__global__ void __launch_bounds__(TPB) __cluster_dims__(NBLK, 1, 1)
l2hist_kernel(const float* __restrict__ target,
              const float* __restrict__ output,
              float* __restrict__ out)
{
    __shared__ alignas(16) int s_cum[6][KBINS];
    __shared__ unsigned int    s_wred[NWARP][3];
    __shared__ alignas(8) unsigned long long s_acc01;  // block 0 only
    __shared__ unsigned int                  s_acc2;   // block 0 only
    __shared__ alignas(8) unsigned long long s_mbar;   // block 0 only

    const int tid  = threadIdx.x;
    const int lane = tid & 31;
    const int warp = tid >> 5;
    const int rank = blockIdx.x;          // == cluster rank (single cluster)

    // Block 0 inits its cluster accumulators + mbarrier. The cluster
    // arrive below (release) + the wait before the reds (acquire) make
    // this visible to all peers before any remote red/arrive can land.
    if (rank == 0 && tid == 0) {
        s_acc01 = 0ULL;
        s_acc2  = 0u;
        asm volatile("mbarrier.init.shared.b64 [%0], %1;"
                     :: "r"(smem_u32(&s_mbar)), "r"(NBLK) : "memory");
    }
    asm volatile("barrier.cluster.arrive.aligned;" ::: "memory");

    // ---- Scan: warp a computes floor(cumsum) of array a. ----
    {
        const float* src = (warp < 3) ? target + (warp << 8)
                                      : output + ((warp - 3) << 8);
        const float4 v0 = __ldg((const float4*)(src + (lane << 3)));
        const float4 v1 = __ldg((const float4*)(src + (lane << 3) + 4));

        float q0 = v0.x;
        float q1 = q0 + v0.y;
        float q2 = q1 + v0.z;
        float q3 = q2 + v0.w;
        float q4 = q3 + v1.x;
        float q5 = q4 + v1.y;
        float q6 = q5 + v1.z;
        float q7 = q6 + v1.w;          // lane total

        float inc = q7;
        #pragma unroll
        for (int off = 1; off < 32; off <<= 1) {
            const float n = __shfl_up_sync(0xFFFFFFFFu, inc, off);
            if (lane >= off) inc += n;
        }
        float excl = __shfl_up_sync(0xFFFFFFFFu, inc, 1);
        if (lane == 0) excl = 0.0f;

        int4 w0, w1;
        w0.x = __float2int_rd(excl + q0);
        w0.y = __float2int_rd(excl + q1);
        w0.z = __float2int_rd(excl + q2);
        w0.w = __float2int_rd(excl + q3);
        w1.x = __float2int_rd(excl + q4);
        w1.y = __float2int_rd(excl + q5);
        w1.z = __float2int_rd(excl + q6);
        w1.w = __float2int_rd(excl + q7);
        *(int4*)&s_cum[warp][(lane << 3)]     = w0;
        *(int4*)&s_cum[warp][(lane << 3) + 4] = w1;
    }
    __syncthreads();

    // ---- One candidate breakpoint per thread. ----
    const int e     = rank * TPB + tid;    // 0..1535
    const int a_src = e >> 8;
    const int j_src = e & (KBINS - 1);
    const int x     = s_cum[a_src][j_src];

    // Saturating searches: s[a] = min(count(cum[a] <= x), 255).
    int s[6];
    #pragma unroll
    for (int a = 0; a < 6; ++a) s[a] = 0;
    #pragma unroll
    for (int w = 128; w; w >>= 1) {
        #pragma unroll
        for (int a = 0; a < 6; ++a)
            if (s_cum[a][s[a] + w - 1] <= x) s[a] += w;
    }

    // Exact counts, presence of x, next breakpoint > x.
    int  cnt[6];
    bool pres[6];
    int  nxt = NPIX;
    #pragma unroll
    for (int a = 0; a < 6; ++a) {
        int c = s[a];
        if (c == KBINS - 1 && s_cum[a][KBINS - 1] <= x) c = KBINS;  // count 256
        cnt[a]  = c;
        pres[a] = (c > 0) && (s_cum[a][c - 1] == x);
        const int nv = (c < KBINS) ? s_cum[a][c] : INT_MAX;
        nxt = (nv < nxt) ? nv : nxt;
    }
    const int len = (nxt > x) ? (nxt - x) : 0;     // nxt already <= NPIX

    // Dedup: only the first occurrence of value x (array order, then index).
    bool canonical = (j_src == 0) || (s_cum[a_src][j_src - 1] < x);
    #pragma unroll
    for (int a = 0; a < 6; ++a)
        if (a < a_src && pres[a]) canonical = false;

    unsigned int acc[3] = {0u, 0u, 0u};
    if (canonical && len > 0) {
        int h1 = 0, h2 = 0;
        #pragma unroll
        for (int c = 0; c < 3; ++c) {
            const int c1 = cnt[c], c2 = cnt[c + 3];
            if (c1 <= KBINS - 2)   h1 = c1;
            else if (c1 == KBINS)  h1 = KBINS - 1;   // count was 256
            /* c1 == 255: keep previous channel's value */
            if (c2 <= KBINS - 2)   h2 = c2;
            else if (c2 == KBINS)  h2 = KBINS - 1;
            const int d = h1 - h2;
            // len*d^2 <= 50176*65025 < 2^32; channel totals are sums over
            // disjoint segments tiling [0, NPIX), so they fit u32 too.
            acc[c] = (unsigned int)len * (unsigned int)(d * d);
        }
    }

    // ---- Warp reduce, stash per-warp partials. ----
    #pragma unroll
    for (int c = 0; c < 3; ++c)
        acc[c] = __reduce_add_sync(0xFFFFFFFFu, acc[c]);
    if (lane == 0) {
        s_wred[warp][0] = acc[0];
        s_wred[warp][1] = acc[1];
        s_wred[warp][2] = acc[2];
    }
    __syncthreads();

    // Cluster wait (acquire): block 0's acc/mbar init is visible. All CTAs
    // arrived at kernel start, so this completes ~immediately.
    asm volatile("barrier.cluster.wait.aligned;" ::: "memory");

    // Leader: sum the 6 warp partials, red into block 0's smem, then a
    // remote mbarrier arrive (release — orders the reds before the arrive).
    if (tid == 0) {
        unsigned int b0 = 0, b1 = 0, b2 = 0;
        #pragma unroll
        for (int w = 0; w < NWARP; ++w) {
            b0 += s_wred[w][0];
            b1 += s_wred[w][1];
            b2 += s_wred[w][2];
        }
        // Channel sums < 2^32 globally: packed u64 add never carries
        // across the 32-bit field boundary.
        const unsigned long long v01 =
            (unsigned long long)b0 | ((unsigned long long)b1 << 32);
        unsigned int r01, r2, rmb;
        const unsigned int l01 = smem_u32(&s_acc01);
        const unsigned int l2  = smem_u32(&s_acc2);
        const unsigned int lmb = smem_u32(&s_mbar);
        asm("mapa.shared::cluster.u32 %0, %1, %2;" : "=r"(r01) : "r"(l01), "r"(0));
        asm("mapa.shared::cluster.u32 %0, %1, %2;" : "=r"(r2)  : "r"(l2),  "r"(0));
        asm("mapa.shared::cluster.u32 %0, %1, %2;" : "=r"(rmb) : "r"(lmb), "r"(0));
        asm volatile("red.relaxed.cluster.shared::cluster.add.u64 [%0], %1;"
                     :: "r"(r01), "l"(v01) : "memory");
        asm volatile("red.relaxed.cluster.shared::cluster.add.u32 [%0], %1;"
                     :: "r"(r2), "r"(b2) : "memory");
        asm volatile("mbarrier.arrive.release.cluster.shared::cluster.b64 _, [%0];"
                     :: "r"(rmb) : "memory");
    }

    // Block 0 finalizes: acquire try_wait on phase 0 (smem mbarrier is
    // re-initialized every launch, so parity is always 0 — replay-safe).
    if (rank == 0 && tid == 0) {
        asm volatile(
            "{\n\t"
            ".reg .pred P;\n\t"
            "LW_%=:\n\t"
            "mbarrier.try_wait.parity.acquire.cluster.shared::cta.b64 P, [%0], 0;\n\t"
            "@!P bra LW_%=;\n\t"
            "}"
            :: "r"(smem_u32(&s_mbar)) : "memory");
        const unsigned long long a01 = s_acc01;
        const unsigned int       a2  = s_acc2;
        *out = sqrtf((float)(unsigned int)(a01 & 0xFFFFFFFFu))
             + sqrtf((float)(unsigned int)(a01 >> 32))
             + sqrtf((float)a2);
    }
}

extern "C" void kernel_launch(void* const* d_in, const int* in_sizes, int n_in,
                              void* d_out, int out_size)
{
    const float* target = (const float*)d_in[0];  // (3, 256, 1) fp32
    const float* output = (const float*)d_in[1];  // (3, 256, 1) fp32
    float* out = (float*)d_out;                   // scalar fp32
    (void)in_sizes; (void)n_in; (void)out_size;

    l2hist_kernel<<<NBLK, TPB>>>(target, output, out);
}

// round 11
// speedup vs baseline: 1.3140x; 1.3140x over previous
#include <cuda_runtime.h>
#include <math.h>
#include <limits.h>

// L2loss over bucketized histograms — analytic segment version (R11).
// Sum_p (h1-h2)^2 = sum over segments [x, next(x)) of len*d^2, candidates =
// the 6*256 cum values, deduped at first occurrence. 8 blocks x 192 threads
// = 1536 = one candidate per thread, launched as ONE CLUSTER.
// R11 tail (minimal): each CTA leader STORES its 3 partials into its own
// private slot in block 0's smem (st.shared::cluster, distinct addresses ->
// no init, no atomics), then ONE cluster barrier round (arrive=release,
// wait=acquire) orders everything; block 0 sums 8 slots locally and writes.

namespace {
constexpr int KBINS = 256;
constexpr int NPIX  = 224 * 224;     // 50176
constexpr int TPB   = 192;           // 6 warps (one per scanned array)
constexpr int NENT  = 6 * KBINS;     // 1536 candidate breakpoints
constexpr int NBLK  = NENT / TPB;    // 8 = cluster size
constexpr int NWARP = TPB / 32;      // 6
}

__device__ __forceinline__ unsigned int smem_u32(const void* p) {
    unsigned int a;
    asm("{ .reg .u64 t; cvta.to.shared.u64 t, %1; cvt.u32.u64 %0, t; }"
        : "=r"(a) : "l"(p));
    return a;
}

__global__ void __launch_bounds__(TPB) __cluster_dims__(NBLK, 1, 1)
l2hist_kernel(const float* __restrict__ target,
              const float* __restrict__ output,
              float* __restrict__ out)
{
    __shared__ alignas(16) int s_cum[6][KBINS];
    __shared__ unsigned int    s_wred[NWARP][3];
    // Per-CTA partial slots, written remotely into block 0's copy:
    // slot r = { ch0|ch1 packed u64 , ch2 u32 , pad }.
    __shared__ alignas(16) unsigned long long s_part01[NBLK];
    __shared__ unsigned int                   s_part2[NBLK];

    const int tid  = threadIdx.x;
    const int lane = tid & 31;
    const int warp = tid >> 5;
    const int rank = blockIdx.x;          // == cluster rank (single cluster)

    // ---- Scan: warp a computes floor(cumsum) of array a. ----
    {
        const float* src = (warp < 3) ? target + (warp << 8)
                                      : output + ((warp - 3) << 8);
        const float4 v0 = __ldg((const float4*)(src + (lane << 3)));
        const float4 v1 = __ldg((const float4*)(src + (lane << 3) + 4));

        float q0 = v0.x;
        float q1 = q0 + v0.y;
        float q2 = q1 + v0.z;
        float q3 = q2 + v0.w;
        float q4 = q3 + v1.x;
        float q5 = q4 + v1.y;
        float q6 = q5 + v1.z;
        float q7 = q6 + v1.w;          // lane total

        float inc = q7;
        #pragma unroll
        for (int off = 1; off < 32; off <<= 1) {
            const float n = __shfl_up_sync(0xFFFFFFFFu, inc, off);
            if (lane >= off) inc += n;
        }
        float excl = __shfl_up_sync(0xFFFFFFFFu, inc, 1);
        if (lane == 0) excl = 0.0f;

        int4 w0, w1;
        w0.x = __float2int_rd(excl + q0);
        w0.y = __float2int_rd(excl + q1);
        w0.z = __float2int_rd(excl + q2);
        w0.w = __float2int_rd(excl + q3);
        w1.x = __float2int_rd(excl + q4);
        w1.y = __float2int_rd(excl + q5);
        w1.z = __float2int_rd(excl + q6);
        w1.w = __float2int_rd(excl + q7);
        *(int4*)&s_cum[warp][(lane << 3)]     = w0;
        *(int4*)&s_cum[warp][(lane << 3) + 4] = w1;
    }
    __syncthreads();

    // ---- One candidate breakpoint per thread. ----
    const int e     = rank * TPB + tid;    // 0..1535
    const int a_src = e >> 8;
    const int j_src = e & (KBINS - 1);
    const int x     = s_cum[a_src][j_src];

    // Saturating searches: s[a] = min(count(cum[a] <= x), 255).
    int s[6];
    #pragma unroll
    for (int a = 0; a < 6; ++a) s[a] = 0;
    #pragma unroll
    for (int w = 128; w; w >>= 1) {
        #pragma unroll
        for (int a = 0; a < 6; ++a)
            if (s_cum[a][s[a] + w - 1] <= x) s[a] += w;
    }

    // Exact counts, presence of x, next breakpoint > x.
    int  cnt[6];
    bool pres[6];
    int  nxt = NPIX;
    #pragma unroll
    for (int a = 0; a < 6; ++a) {
        int c = s[a];
        if (c == KBINS - 1 && s_cum[a][KBINS - 1] <= x) c = KBINS;  // count 256
        cnt[a]  = c;
        pres[a] = (c > 0) && (s_cum[a][c - 1] == x);
        const int nv = (c < KBINS) ? s_cum[a][c] : INT_MAX;
        nxt = (nv < nxt) ? nv : nxt;
    }
    const int len = (nxt > x) ? (nxt - x) : 0;     // nxt already <= NPIX

    // Dedup: only the first occurrence of value x (array order, then index).
    bool canonical = (j_src == 0) || (s_cum[a_src][j_src - 1] < x);
    #pragma unroll
    for (int a = 0; a < 6; ++a)
        if (a < a_src && pres[a]) canonical = false;

    unsigned int acc[3] = {0u, 0u, 0u};
    if (canonical && len > 0) {
        int h1 = 0, h2 = 0;
        #pragma unroll
        for (int c = 0; c < 3; ++c) {
            const int c1 = cnt[c], c2 = cnt[c + 3];
            if (c1 <= KBINS - 2)   h1 = c1;
            else if (c1 == KBINS)  h1 = KBINS - 1;   // count was 256
            /* c1 == 255: keep previous channel's value */
            if (c2 <= KBINS - 2)   h2 = c2;
            else if (c2 == KBINS)  h2 = KBINS - 1;
            const int d = h1 - h2;
            // len*d^2 <= 50176*65025 < 2^32; channel totals are sums over
            // disjoint segments tiling [0, NPIX), so they fit u32 too.
            acc[c] = (unsigned int)len * (unsigned int)(d * d);
        }
    }

    // ---- Warp reduce, stash per-warp partials. ----
    #pragma unroll
    for (int c = 0; c < 3; ++c)
        acc[c] = __reduce_add_sync(0xFFFFFFFFu, acc[c]);
    if (lane == 0) {
        s_wred[warp][0] = acc[0];
        s_wred[warp][1] = acc[1];
        s_wred[warp][2] = acc[2];
    }
    __syncthreads();

    // Leader: sum the 6 warp partials and store them into THIS CTA's private
    // slot inside block 0's smem (distinct addresses -> no init, no atomics).
    if (tid == 0) {
        unsigned int b0 = 0, b1 = 0, b2 = 0;
        #pragma unroll
        for (int w = 0; w < NWARP; ++w) {
            b0 += s_wred[w][0];
            b1 += s_wred[w][1];
            b2 += s_wred[w][2];
        }
        const unsigned long long v01 =
            (unsigned long long)b0 | ((unsigned long long)b1 << 32);
        unsigned int r01, r2;
        const unsigned int l01 = smem_u32(&s_part01[rank]);
        const unsigned int l2  = smem_u32(&s_part2[rank]);
        asm("mapa.shared::cluster.u32 %0, %1, %2;" : "=r"(r01) : "r"(l01), "r"(0));
        asm("mapa.shared::cluster.u32 %0, %1, %2;" : "=r"(r2)  : "r"(l2),  "r"(0));
        asm volatile("st.shared::cluster.u64 [%0], %1;"
                     :: "r"(r01), "l"(v01) : "memory");
        asm volatile("st.shared::cluster.u32 [%0], %1;"
                     :: "r"(r2), "r"(b2) : "memory");
    }

    // Single cluster barrier round: arrive is a release (orders the slot
    // stores above), wait is an acquire (block 0 sees all 8 slots).
    asm volatile("barrier.cluster.arrive.aligned;" ::: "memory");
    asm volatile("barrier.cluster.wait.aligned;"   ::: "memory");

    if (rank == 0 && tid == 0) {
        unsigned int t0 = 0, t1 = 0, t2 = 0;
        #pragma unroll
        for (int r = 0; r < NBLK; ++r) {
            const unsigned long long v01 = s_part01[r];
            t0 += (unsigned int)(v01 & 0xFFFFFFFFu);
            t1 += (unsigned int)(v01 >> 32);
            t2 += s_part2[r];
        }
        *out = sqrtf((float)t0) + sqrtf((float)t1) + sqrtf((float)t2);
    }
}

extern "C" void kernel_launch(void* const* d_in, const int* in_sizes, int n_in,
                              void* d_out, int out_size)
{
    const float* target = (const float*)d_in[0];  // (3, 256, 1) fp32
    const float* output = (const float*)d_in[1];  // (3, 256, 1) fp32
    float* out = (float*)d_out;                   // scalar fp32
    (void)in_sizes; (void)n_in; (void)out_size;

    l2hist_kernel<<<NBLK, TPB>>>(target, output, out);
}